// round 9
// baseline (speedup 1.0000x reference)
#include <cuda_runtime.h>
#include <math.h>
#include <float.h>
#include <stdint.h>

#define NPTS   262144
#define DIMS   128
#define K      120
#define KP     128
#define BP     128
#define NTILES (NPTS / BP)   // 2048
#define NSETS  2
#define GRID_ASSIGN 148
#define INV_T  2.5f
#define LDM    136           // smem row stride in floats (conflict-free float2 frags)

// --------------------------- persistent device state ------------------------
__device__ float g_c[NSETS][K * DIMS];
__device__ float g_csqh[NSETS][KP];
__device__ float g_counts_unused;  // (kept minimal)
__device__ int   g_cl[NSETS][NPTS];
__device__ float g_loss[NSETS];
// per-CTA partials (no zeroing needed: every CTA overwrites fully each pass)
__device__ float g_part_sums[GRID_ASSIGN][KP * DIMS];
__device__ float g_part_cnt[GRID_ASSIGN][KP];

// --------------------------- helpers ----------------------------------------
__device__ __forceinline__ float f2tf32(float f) {
    uint32_t r;
    asm("cvt.rna.tf32.f32 %0, %1;" : "=r"(r) : "f"(f));
    return __uint_as_float(r);
}

// m16n8k8 tf32 MMA (CUTLASS SM80_16x8x8_F32TF32TF32F32_TN layouts):
//  g = lane>>2, t = lane&3
//  A(row-major m16 x k8): a0=(g,2t) a1=(g,2t+1) a2=(g+8,2t) a3=(g+8,2t+1)
//  B(col-major k8 x n8):  b0=(k=2t,n=g) b1=(k=2t+1,n=g)
//  C: c0=(g,2t) c1=(g,2t+1) c2=(g+8,2t) c3=(g+8,2t+1)
__device__ __forceinline__ void mma8(float* c, float2 a01, float2 a23, float2 b) {
    asm volatile(
        "mma.sync.aligned.m16n8k8.row.col.f32.tf32.tf32.f32 "
        "{%0,%1,%2,%3}, {%4,%5,%6,%7}, {%8,%9}, {%0,%1,%2,%3};"
        : "+f"(c[0]), "+f"(c[1]), "+f"(c[2]), "+f"(c[3])
        : "r"(__float_as_uint(a01.x)), "r"(__float_as_uint(a01.y)),
          "r"(__float_as_uint(a23.x)), "r"(__float_as_uint(a23.y)),
          "r"(__float_as_uint(b.x)),   "r"(__float_as_uint(b.y)));
}

// --------------------------- small kernels ----------------------------------
__global__ void init_centroids(const float* __restrict__ x, int s) {
    int k = blockIdx.x, d = threadIdx.x;
    float v = x[k * DIMS + d];
    g_c[s][k * DIMS + d] = v;
    __shared__ float red[DIMS];
    red[d] = v * v;
    __syncthreads();
    for (int t = 64; t > 0; t >>= 1) { if (d < t) red[d] += red[d + t]; __syncthreads(); }
    if (d == 0) g_csqh[s][k] = 0.5f * red[0];
}

// reduce 148 per-CTA partials -> new centroids
__global__ void update_centroids(int s) {
    int k = blockIdx.x, d = threadIdx.x;   // grid K, block DIMS
    float sum = 0.f;
#pragma unroll 4
    for (int i = 0; i < GRID_ASSIGN; ++i) sum += g_part_sums[i][k * DIMS + d];

    __shared__ float scnt;
    if (d < 32) {
        float c = 0.f;
        for (int i = d; i < GRID_ASSIGN; i += 32) c += g_part_cnt[i][k];
        for (int o = 16; o; o >>= 1) c += __shfl_down_sync(0xffffffffu, c, o);
        if (d == 0) scnt = c;
    }
    __syncthreads();
    float cnt = scnt;
    float div = (cnt == 0.f) ? 1.f : cnt;
    float v = sum / div;
    g_c[s][k * DIMS + d] = v;

    __shared__ float red[DIMS];
    red[d] = v * v;
    __syncthreads();
    for (int t = 64; t > 0; t >>= 1) { if (d < t) red[d] += red[d + t]; __syncthreads(); }
    if (d == 0) g_csqh[s][k] = 0.5f * red[0];
}

__global__ void zero_loss_k() { if (threadIdx.x < NSETS) g_loss[threadIdx.x] = 0.f; }

__global__ void write_out(float* out) {
    out[0] = (g_loss[0] + g_loss[1]) * (0.5f / (float)NPTS);
}

// --------------------------- assignment pass (persistent) -------------------
// Dyn smem: sx[128*LDM] | sc[128*LDM]
// MMA1: logits = X . C^T  -> argmin epilogue -> s_cl
// MMA2: sums += X^T . onehot(s_cl)  (register accumulation across tiles)
__global__ void __launch_bounds__(256, 1)
assign_kernel(const float* __restrict__ x, int cs, int rev) {
    extern __shared__ float sh[];
    float* sx = sh;
    float* sc = sx + BP * LDM;

    __shared__ float s_csq[KP];
    __shared__ float s_cnt[KP];
    __shared__ int   s_cl[BP];

    const int tid  = threadIdx.x;
    const int wid  = tid >> 5;
    const int lane = tid & 31;
    const int g    = lane >> 2;
    const int t    = lane & 3;
    const int m0   = wid * 16;

    if (tid < KP) {
        s_csq[tid] = (tid < K) ? g_csqh[cs][tid] : 3.0e38f;
        s_cnt[tid] = 0.f;
    }
    // centroid tile (tf32), pad rows zero
    for (int i = tid; i < KP * 32; i += 256) {
        int k = i >> 5, d4 = (i & 31) << 2;
        float4 v = make_float4(0.f, 0.f, 0.f, 0.f);
        if (k < K) v = *reinterpret_cast<const float4*>(&g_c[cs][k * DIMS + d4]);
        float* dst = &sc[k * LDM + d4];
        dst[0] = f2tf32(v.x); dst[1] = f2tf32(v.y);
        dst[2] = f2tf32(v.z); dst[3] = f2tf32(v.w);
    }
    __syncthreads();

    // persistent cluster-sum accumulators: dims [m0+g, m0+g+8] x clusters [8j+2t(+1)]
    float acc2[16][4];
#pragma unroll
    for (int j = 0; j < 16; ++j)
#pragma unroll
        for (int v = 0; v < 4; ++v) acc2[j][v] = 0.f;

    for (int tr = blockIdx.x; tr < NTILES; tr += gridDim.x) {
        const int tile = rev ? (NTILES - 1 - tr) : tr;
        const int pbase = tile * BP;

        // stage X tile (tf32)
        for (int i = tid; i < BP * 32; i += 256) {
            int p = i >> 5, d4 = (i & 31) << 2;
            float4 v = *reinterpret_cast<const float4*>(&x[(size_t)(pbase + p) * DIMS + d4]);
            float* dst = &sx[p * LDM + d4];
            dst[0] = f2tf32(v.x); dst[1] = f2tf32(v.y);
            dst[2] = f2tf32(v.z); dst[3] = f2tf32(v.w);
        }
        __syncthreads();

        // MMA1: warp rows [m0, m0+16) x all 128 clusters
        float acc[16][4];
#pragma unroll
        for (int j = 0; j < 16; ++j)
#pragma unroll
            for (int v = 0; v < 4; ++v) acc[j][v] = 0.f;

        {
            const float* ax0 = &sx[(m0 + g) * LDM + 2 * t];
            const float* ax1 = &sx[(m0 + g + 8) * LDM + 2 * t];
            const float* bx  = &sc[g * LDM + 2 * t];
#pragma unroll
            for (int ks = 0; ks < 16; ++ks) {
                float2 a01 = *reinterpret_cast<const float2*>(ax0 + ks * 8);
                float2 a23 = *reinterpret_cast<const float2*>(ax1 + ks * 8);
#pragma unroll
                for (int j = 0; j < 16; ++j) {
                    float2 b = *reinterpret_cast<const float2*>(bx + j * 8 * LDM + ks * 8);
                    mma8(acc[j], a01, a23, b);
                }
            }
        }

        // argmax over k of (dot - 0.5||c||^2); ties -> lowest k
        float best_lo = -FLT_MAX, best_hi = -FLT_MAX;
        int   bk_lo = 0x7FFFFFFF, bk_hi = 0x7FFFFFFF;
#pragma unroll
        for (int j = 0; j < 16; ++j) {
            int c0 = j * 8 + 2 * t;
            float q0 = s_csq[c0], q1 = s_csq[c0 + 1];
            float s0 = acc[j][0] - q0, s1 = acc[j][1] - q1;
            float s2 = acc[j][2] - q0, s3 = acc[j][3] - q1;
            if (s0 > best_lo || (s0 == best_lo && c0     < bk_lo)) { best_lo = s0; bk_lo = c0; }
            if (s1 > best_lo || (s1 == best_lo && c0 + 1 < bk_lo)) { best_lo = s1; bk_lo = c0 + 1; }
            if (s2 > best_hi || (s2 == best_hi && c0     < bk_hi)) { best_hi = s2; bk_hi = c0; }
            if (s3 > best_hi || (s3 == best_hi && c0 + 1 < bk_hi)) { best_hi = s3; bk_hi = c0 + 1; }
        }
#pragma unroll
        for (int off = 1; off <= 2; off <<= 1) {
            float ob = __shfl_xor_sync(0xffffffffu, best_lo, off);
            int   ok = __shfl_xor_sync(0xffffffffu, bk_lo,   off);
            if (ob > best_lo || (ob == best_lo && ok < bk_lo)) { best_lo = ob; bk_lo = ok; }
            ob = __shfl_xor_sync(0xffffffffu, best_hi, off);
            ok = __shfl_xor_sync(0xffffffffu, bk_hi,   off);
            if (ob > best_hi || (ob == best_hi && ok < bk_hi)) { best_hi = ob; bk_hi = ok; }
        }
        if (t == 0) {
            int rlo = m0 + g, rhi = m0 + g + 8;
            s_cl[rlo] = bk_lo; s_cl[rhi] = bk_hi;
            g_cl[cs][pbase + rlo] = bk_lo;
            g_cl[cs][pbase + rhi] = bk_hi;
            atomicAdd(&s_cnt[bk_lo], 1.0f);
            atomicAdd(&s_cnt[bk_hi], 1.0f);
        }
        __syncthreads();  // s_cl ready for MMA2

        // MMA2: sums[dim][cluster] += X^T . onehot
        //   A = X^T (m16 dims x k8 points), B = onehot (k8 points x n8 clusters)
#pragma unroll
        for (int ks = 0; ks < 16; ++ks) {
            const int p0 = 8 * ks + 2 * t;
            float2 a01, a23;
            a01.x = sx[p0 * LDM + m0 + g];
            a01.y = sx[(p0 + 1) * LDM + m0 + g];
            a23.x = sx[p0 * LDM + m0 + g + 8];
            a23.y = sx[(p0 + 1) * LDM + m0 + g + 8];
            const int cl0 = s_cl[p0], cl1 = s_cl[p0 + 1];
#pragma unroll
            for (int j = 0; j < 16; ++j) {
                const int n0 = j * 8 + g;
                float2 b;
                b.x = (cl0 == n0) ? 1.f : 0.f;
                b.y = (cl1 == n0) ? 1.f : 0.f;
                mma8(acc2[j], a01, a23, b);
            }
        }
        __syncthreads();  // protect sx / s_cl before next tile
    }

    // flush per-CTA partials (plain stores; coalesced 32B segments)
    float* ps = g_part_sums[blockIdx.x];
#pragma unroll
    for (int j = 0; j < 16; ++j) {
        const int k0 = j * 8 + 2 * t;
        ps[k0 * DIMS + m0 + g]           = acc2[j][0];
        ps[(k0 + 1) * DIMS + m0 + g]     = acc2[j][1];
        ps[k0 * DIMS + m0 + g + 8]       = acc2[j][2];
        ps[(k0 + 1) * DIMS + m0 + g + 8] = acc2[j][3];
    }
    if (tid < KP) g_part_cnt[blockIdx.x][tid] = (tid < K) ? s_cnt[tid] : 0.f;
}

// --------------------------- cross-entropy pass (persistent) ----------------
__global__ void __launch_bounds__(256, 1)
ce_kernel(const float* __restrict__ x, int cs, int li, int rev) {
    extern __shared__ float sh[];
    float* sx = sh;
    float* sc = sx + BP * LDM;

    __shared__ float s_loss;

    const int tid  = threadIdx.x;
    const int wid  = tid >> 5;
    const int lane = tid & 31;
    const int g    = lane >> 2;
    const int t    = lane & 3;
    const int m0   = wid * 16;

    if (tid == 0) s_loss = 0.f;
    for (int i = tid; i < KP * 32; i += 256) {
        int k = i >> 5, d4 = (i & 31) << 2;
        float4 v = make_float4(0.f, 0.f, 0.f, 0.f);
        if (k < K) v = *reinterpret_cast<const float4*>(&g_c[cs][k * DIMS + d4]);
        float* dst = &sc[k * LDM + d4];
        dst[0] = f2tf32(v.x); dst[1] = f2tf32(v.y);
        dst[2] = f2tf32(v.z); dst[3] = f2tf32(v.w);
    }
    __syncthreads();

    for (int tr = blockIdx.x; tr < NTILES; tr += gridDim.x) {
        const int tile = rev ? (NTILES - 1 - tr) : tr;
        const int pbase = tile * BP;

        for (int i = tid; i < BP * 32; i += 256) {
            int p = i >> 5, d4 = (i & 31) << 2;
            float4 v = *reinterpret_cast<const float4*>(&x[(size_t)(pbase + p) * DIMS + d4]);
            float* dst = &sx[p * LDM + d4];
            dst[0] = f2tf32(v.x); dst[1] = f2tf32(v.y);
            dst[2] = f2tf32(v.z); dst[3] = f2tf32(v.w);
        }
        __syncthreads();

        float acc[16][4];
#pragma unroll
        for (int j = 0; j < 16; ++j)
#pragma unroll
            for (int v = 0; v < 4; ++v) acc[j][v] = 0.f;

        {
            const float* ax0 = &sx[(m0 + g) * LDM + 2 * t];
            const float* ax1 = &sx[(m0 + g + 8) * LDM + 2 * t];
            const float* bx  = &sc[g * LDM + 2 * t];
#pragma unroll
            for (int ks = 0; ks < 16; ++ks) {
                float2 a01 = *reinterpret_cast<const float2*>(ax0 + ks * 8);
                float2 a23 = *reinterpret_cast<const float2*>(ax1 + ks * 8);
#pragma unroll
                for (int j = 0; j < 16; ++j) {
                    float2 b = *reinterpret_cast<const float2*>(bx + j * 8 * LDM + ks * 8);
                    mma8(acc[j], a01, a23, b);
                }
            }
        }

        const int rlo = m0 + g, rhi = m0 + g + 8;
        const int lab_lo = g_cl[cs][pbase + rlo];
        const int lab_hi = g_cl[cs][pbase + rhi];

        float m_lo = -FLT_MAX, m_hi = -FLT_MAX, ll_lo = -FLT_MAX, ll_hi = -FLT_MAX;
#pragma unroll
        for (int j = 0; j < 16; ++j) {
            int c0 = j * 8 + 2 * t;
#pragma unroll
            for (int v = 0; v < 2; ++v) {
                int c = c0 + v;
                if (c < K) {
                    float l0 = acc[j][v]     * INV_T;
                    float l1 = acc[j][v + 2] * INV_T;
                    m_lo = fmaxf(m_lo, l0);
                    m_hi = fmaxf(m_hi, l1);
                    if (c == lab_lo) ll_lo = l0;
                    if (c == lab_hi) ll_hi = l1;
                }
            }
        }
#pragma unroll
        for (int off = 1; off <= 2; off <<= 1) {
            m_lo  = fmaxf(m_lo,  __shfl_xor_sync(0xffffffffu, m_lo,  off));
            m_hi  = fmaxf(m_hi,  __shfl_xor_sync(0xffffffffu, m_hi,  off));
            ll_lo = fmaxf(ll_lo, __shfl_xor_sync(0xffffffffu, ll_lo, off));
            ll_hi = fmaxf(ll_hi, __shfl_xor_sync(0xffffffffu, ll_hi, off));
        }

        float es_lo = 0.f, es_hi = 0.f;
#pragma unroll
        for (int j = 0; j < 16; ++j) {
            int c0 = j * 8 + 2 * t;
#pragma unroll
            for (int v = 0; v < 2; ++v) {
                int c = c0 + v;
                if (c < K) {
                    es_lo += expf(acc[j][v]     * INV_T - m_lo);
                    es_hi += expf(acc[j][v + 2] * INV_T - m_hi);
                }
            }
        }
#pragma unroll
        for (int off = 1; off <= 2; off <<= 1) {
            es_lo += __shfl_xor_sync(0xffffffffu, es_lo, off);
            es_hi += __shfl_xor_sync(0xffffffffu, es_hi, off);
        }

        if (t == 0) {
            float term = (m_lo + logf(es_lo)) - ll_lo
                       + (m_hi + logf(es_hi)) - ll_hi;
            atomicAdd(&s_loss, term);
        }
        __syncthreads();  // protect sx before next stage
    }

    if (tid == 0) atomicAdd(&g_loss[li], s_loss);
}

// --------------------------- launch ------------------------------------------
extern "C" void kernel_launch(void* const* d_in, const int* in_sizes, int n_in,
                              void* d_out, int out_size) {
    const float* f1 = (const float*)d_in[0];
    const float* f2 = (const float*)d_in[1];
    float* out = (float*)d_out;

    const int smem = (BP * LDM + KP * LDM) * sizeof(float);  // ~139 KB
    cudaFuncSetAttribute(assign_kernel, cudaFuncAttributeMaxDynamicSharedMemorySize, smem);
    cudaFuncSetAttribute(ce_kernel,     cudaFuncAttributeMaxDynamicSharedMemorySize, smem);

    init_centroids<<<K, DIMS>>>(f1, 0);
    init_centroids<<<K, DIMS>>>(f2, 1);

    // all iterations of set 0 first, then set 1 (L2 reuse); serpentine per iter
    for (int s = 0; s < 2; ++s) {
        const float* x = s ? f2 : f1;
        for (int it = 0; it < 5; ++it) {
            assign_kernel<<<GRID_ASSIGN, 256, smem>>>(x, s, it & 1);
            update_centroids<<<K, DIMS>>>(s);
        }
    }

    zero_loss_k<<<1, 32>>>();
    // f2 is L2-hot after set-1 iterations: run its CE first (reverse order)
    // loss2 = CE(f2 @ c1 vs cl1) -> set cs=0, li=1 ; loss1 = CE(f1 @ c2 vs cl2)
    ce_kernel<<<GRID_ASSIGN, 256, smem>>>(f2, 0, 1, 1);
    ce_kernel<<<GRID_ASSIGN, 256, smem>>>(f1, 1, 0, 0);
    write_out<<<1, 1>>>(out);
}

// round 12
// speedup vs baseline: 1.0146x; 1.0146x over previous
#include <cuda_runtime.h>
#include <math.h>
#include <float.h>
#include <stdint.h>

#define NPTS   262144
#define DIMS   128
#define K      120
#define KP     128
#define BP     128
#define NTILES (NPTS / BP)   // 2048
#define NSETS  2
#define GRID_ASSIGN 148
#define INV_T  2.5f
#define LDM    136           // smem row stride in floats (conflict-free float2 frags)

// --------------------------- persistent device state ------------------------
__device__ float g_c[NSETS][K * DIMS];
__device__ float g_csqh[NSETS][KP];
__device__ float g_counts_unused;  // (kept minimal)
__device__ int   g_cl[NSETS][NPTS];
__device__ float g_loss[NSETS];
// per-CTA partials (no zeroing needed: every CTA overwrites fully each pass)
__device__ float g_part_sums[GRID_ASSIGN][KP * DIMS];
__device__ float g_part_cnt[GRID_ASSIGN][KP];

// --------------------------- helpers ----------------------------------------
__device__ __forceinline__ float f2tf32(float f) {
    uint32_t r;
    asm("cvt.rna.tf32.f32 %0, %1;" : "=r"(r) : "f"(f));
    return __uint_as_float(r);
}

// m16n8k8 tf32 MMA (CUTLASS SM80_16x8x8_F32TF32TF32F32_TN layouts):
//  g = lane>>2, t = lane&3
//  A(row-major m16 x k8): a0=(g,2t) a1=(g,2t+1) a2=(g+8,2t) a3=(g+8,2t+1)
//  B(col-major k8 x n8):  b0=(k=2t,n=g) b1=(k=2t+1,n=g)
//  C: c0=(g,2t) c1=(g,2t+1) c2=(g+8,2t) c3=(g+8,2t+1)
__device__ __forceinline__ void mma8(float* c, float2 a01, float2 a23, float2 b) {
    asm volatile(
        "mma.sync.aligned.m16n8k8.row.col.f32.tf32.tf32.f32 "
        "{%0,%1,%2,%3}, {%4,%5,%6,%7}, {%8,%9}, {%0,%1,%2,%3};"
        : "+f"(c[0]), "+f"(c[1]), "+f"(c[2]), "+f"(c[3])
        : "r"(__float_as_uint(a01.x)), "r"(__float_as_uint(a01.y)),
          "r"(__float_as_uint(a23.x)), "r"(__float_as_uint(a23.y)),
          "r"(__float_as_uint(b.x)),   "r"(__float_as_uint(b.y)));
}

// --------------------------- small kernels ----------------------------------
__global__ void init_centroids(const float* __restrict__ x, int s) {
    int k = blockIdx.x, d = threadIdx.x;
    float v = x[k * DIMS + d];
    g_c[s][k * DIMS + d] = v;
    __shared__ float red[DIMS];
    red[d] = v * v;
    __syncthreads();
    for (int t = 64; t > 0; t >>= 1) { if (d < t) red[d] += red[d + t]; __syncthreads(); }
    if (d == 0) g_csqh[s][k] = 0.5f * red[0];
}

// reduce 148 per-CTA partials -> new centroids
__global__ void update_centroids(int s) {
    int k = blockIdx.x, d = threadIdx.x;   // grid K, block DIMS
    float sum = 0.f;
#pragma unroll 4
    for (int i = 0; i < GRID_ASSIGN; ++i) sum += g_part_sums[i][k * DIMS + d];

    __shared__ float scnt;
    if (d < 32) {
        float c = 0.f;
        for (int i = d; i < GRID_ASSIGN; i += 32) c += g_part_cnt[i][k];
        for (int o = 16; o; o >>= 1) c += __shfl_down_sync(0xffffffffu, c, o);
        if (d == 0) scnt = c;
    }
    __syncthreads();
    float cnt = scnt;
    float div = (cnt == 0.f) ? 1.f : cnt;
    float v = sum / div;
    g_c[s][k * DIMS + d] = v;

    __shared__ float red[DIMS];
    red[d] = v * v;
    __syncthreads();
    for (int t = 64; t > 0; t >>= 1) { if (d < t) red[d] += red[d + t]; __syncthreads(); }
    if (d == 0) g_csqh[s][k] = 0.5f * red[0];
}

__global__ void zero_loss_k() { if (threadIdx.x < NSETS) g_loss[threadIdx.x] = 0.f; }

__global__ void write_out(float* out) {
    out[0] = (g_loss[0] + g_loss[1]) * (0.5f / (float)NPTS);
}

// --------------------------- assignment pass (persistent) -------------------
// Dyn smem: sx[128*LDM] | sc[128*LDM]
// MMA1: logits = X . C^T  -> argmin epilogue -> s_cl
// MMA2: sums += X^T . onehot(s_cl)  (register accumulation across tiles)
__global__ void __launch_bounds__(256, 1)
assign_kernel(const float* __restrict__ x, int cs, int rev) {
    extern __shared__ float sh[];
    float* sx = sh;
    float* sc = sx + BP * LDM;

    __shared__ float s_csq[KP];
    __shared__ float s_cnt[KP];
    __shared__ int   s_cl[BP];

    const int tid  = threadIdx.x;
    const int wid  = tid >> 5;
    const int lane = tid & 31;
    const int g    = lane >> 2;
    const int t    = lane & 3;
    const int m0   = wid * 16;

    if (tid < KP) {
        s_csq[tid] = (tid < K) ? g_csqh[cs][tid] : 3.0e38f;
        s_cnt[tid] = 0.f;
    }
    // centroid tile (tf32), pad rows zero
    for (int i = tid; i < KP * 32; i += 256) {
        int k = i >> 5, d4 = (i & 31) << 2;
        float4 v = make_float4(0.f, 0.f, 0.f, 0.f);
        if (k < K) v = *reinterpret_cast<const float4*>(&g_c[cs][k * DIMS + d4]);
        float* dst = &sc[k * LDM + d4];
        dst[0] = f2tf32(v.x); dst[1] = f2tf32(v.y);
        dst[2] = f2tf32(v.z); dst[3] = f2tf32(v.w);
    }
    __syncthreads();

    // persistent cluster-sum accumulators: dims [m0+g, m0+g+8] x clusters [8j+2t(+1)]
    float acc2[16][4];
#pragma unroll
    for (int j = 0; j < 16; ++j)
#pragma unroll
        for (int v = 0; v < 4; ++v) acc2[j][v] = 0.f;

    for (int tr = blockIdx.x; tr < NTILES; tr += gridDim.x) {
        const int tile = rev ? (NTILES - 1 - tr) : tr;
        const int pbase = tile * BP;

        // stage X tile (tf32)
        for (int i = tid; i < BP * 32; i += 256) {
            int p = i >> 5, d4 = (i & 31) << 2;
            float4 v = *reinterpret_cast<const float4*>(&x[(size_t)(pbase + p) * DIMS + d4]);
            float* dst = &sx[p * LDM + d4];
            dst[0] = f2tf32(v.x); dst[1] = f2tf32(v.y);
            dst[2] = f2tf32(v.z); dst[3] = f2tf32(v.w);
        }
        __syncthreads();

        // MMA1: warp rows [m0, m0+16) x all 128 clusters
        float acc[16][4];
#pragma unroll
        for (int j = 0; j < 16; ++j)
#pragma unroll
            for (int v = 0; v < 4; ++v) acc[j][v] = 0.f;

        {
            const float* ax0 = &sx[(m0 + g) * LDM + 2 * t];
            const float* ax1 = &sx[(m0 + g + 8) * LDM + 2 * t];
            const float* bx  = &sc[g * LDM + 2 * t];
#pragma unroll
            for (int ks = 0; ks < 16; ++ks) {
                float2 a01 = *reinterpret_cast<const float2*>(ax0 + ks * 8);
                float2 a23 = *reinterpret_cast<const float2*>(ax1 + ks * 8);
#pragma unroll
                for (int j = 0; j < 16; ++j) {
                    float2 b = *reinterpret_cast<const float2*>(bx + j * 8 * LDM + ks * 8);
                    mma8(acc[j], a01, a23, b);
                }
            }
        }

        // argmax over k of (dot - 0.5||c||^2); ties -> lowest k
        float best_lo = -FLT_MAX, best_hi = -FLT_MAX;
        int   bk_lo = 0x7FFFFFFF, bk_hi = 0x7FFFFFFF;
#pragma unroll
        for (int j = 0; j < 16; ++j) {
            int c0 = j * 8 + 2 * t;
            float q0 = s_csq[c0], q1 = s_csq[c0 + 1];
            float s0 = acc[j][0] - q0, s1 = acc[j][1] - q1;
            float s2 = acc[j][2] - q0, s3 = acc[j][3] - q1;
            if (s0 > best_lo || (s0 == best_lo && c0     < bk_lo)) { best_lo = s0; bk_lo = c0; }
            if (s1 > best_lo || (s1 == best_lo && c0 + 1 < bk_lo)) { best_lo = s1; bk_lo = c0 + 1; }
            if (s2 > best_hi || (s2 == best_hi && c0     < bk_hi)) { best_hi = s2; bk_hi = c0; }
            if (s3 > best_hi || (s3 == best_hi && c0 + 1 < bk_hi)) { best_hi = s3; bk_hi = c0 + 1; }
        }
#pragma unroll
        for (int off = 1; off <= 2; off <<= 1) {
            float ob = __shfl_xor_sync(0xffffffffu, best_lo, off);
            int   ok = __shfl_xor_sync(0xffffffffu, bk_lo,   off);
            if (ob > best_lo || (ob == best_lo && ok < bk_lo)) { best_lo = ob; bk_lo = ok; }
            ob = __shfl_xor_sync(0xffffffffu, best_hi, off);
            ok = __shfl_xor_sync(0xffffffffu, bk_hi,   off);
            if (ob > best_hi || (ob == best_hi && ok < bk_hi)) { best_hi = ob; bk_hi = ok; }
        }
        if (t == 0) {
            int rlo = m0 + g, rhi = m0 + g + 8;
            s_cl[rlo] = bk_lo; s_cl[rhi] = bk_hi;
            g_cl[cs][pbase + rlo] = bk_lo;
            g_cl[cs][pbase + rhi] = bk_hi;
            atomicAdd(&s_cnt[bk_lo], 1.0f);
            atomicAdd(&s_cnt[bk_hi], 1.0f);
        }
        __syncthreads();  // s_cl ready for MMA2

        // MMA2: sums[dim][cluster] += X^T . onehot
        //   A = X^T (m16 dims x k8 points), B = onehot (k8 points x n8 clusters)
#pragma unroll
        for (int ks = 0; ks < 16; ++ks) {
            const int p0 = 8 * ks + 2 * t;
            float2 a01, a23;
            a01.x = sx[p0 * LDM + m0 + g];
            a01.y = sx[(p0 + 1) * LDM + m0 + g];
            a23.x = sx[p0 * LDM + m0 + g + 8];
            a23.y = sx[(p0 + 1) * LDM + m0 + g + 8];
            const int cl0 = s_cl[p0], cl1 = s_cl[p0 + 1];
#pragma unroll
            for (int j = 0; j < 16; ++j) {
                const int n0 = j * 8 + g;
                float2 b;
                b.x = (cl0 == n0) ? 1.f : 0.f;
                b.y = (cl1 == n0) ? 1.f : 0.f;
                mma8(acc2[j], a01, a23, b);
            }
        }
        __syncthreads();  // protect sx / s_cl before next tile
    }

    // flush per-CTA partials (plain stores; coalesced 32B segments)
    float* ps = g_part_sums[blockIdx.x];
#pragma unroll
    for (int j = 0; j < 16; ++j) {
        const int k0 = j * 8 + 2 * t;
        ps[k0 * DIMS + m0 + g]           = acc2[j][0];
        ps[(k0 + 1) * DIMS + m0 + g]     = acc2[j][1];
        ps[k0 * DIMS + m0 + g + 8]       = acc2[j][2];
        ps[(k0 + 1) * DIMS + m0 + g + 8] = acc2[j][3];
    }
    if (tid < KP) g_part_cnt[blockIdx.x][tid] = (tid < K) ? s_cnt[tid] : 0.f;
}

// --------------------------- cross-entropy pass (persistent) ----------------
__global__ void __launch_bounds__(256, 1)
ce_kernel(const float* __restrict__ x, int cs, int li, int rev) {
    extern __shared__ float sh[];
    float* sx = sh;
    float* sc = sx + BP * LDM;

    __shared__ float s_loss;

    const int tid  = threadIdx.x;
    const int wid  = tid >> 5;
    const int lane = tid & 31;
    const int g    = lane >> 2;
    const int t    = lane & 3;
    const int m0   = wid * 16;

    if (tid == 0) s_loss = 0.f;
    for (int i = tid; i < KP * 32; i += 256) {
        int k = i >> 5, d4 = (i & 31) << 2;
        float4 v = make_float4(0.f, 0.f, 0.f, 0.f);
        if (k < K) v = *reinterpret_cast<const float4*>(&g_c[cs][k * DIMS + d4]);
        float* dst = &sc[k * LDM + d4];
        dst[0] = f2tf32(v.x); dst[1] = f2tf32(v.y);
        dst[2] = f2tf32(v.z); dst[3] = f2tf32(v.w);
    }
    __syncthreads();

    for (int tr = blockIdx.x; tr < NTILES; tr += gridDim.x) {
        const int tile = rev ? (NTILES - 1 - tr) : tr;
        const int pbase = tile * BP;

        for (int i = tid; i < BP * 32; i += 256) {
            int p = i >> 5, d4 = (i & 31) << 2;
            float4 v = *reinterpret_cast<const float4*>(&x[(size_t)(pbase + p) * DIMS + d4]);
            float* dst = &sx[p * LDM + d4];
            dst[0] = f2tf32(v.x); dst[1] = f2tf32(v.y);
            dst[2] = f2tf32(v.z); dst[3] = f2tf32(v.w);
        }
        __syncthreads();

        float acc[16][4];
#pragma unroll
        for (int j = 0; j < 16; ++j)
#pragma unroll
            for (int v = 0; v < 4; ++v) acc[j][v] = 0.f;

        {
            const float* ax0 = &sx[(m0 + g) * LDM + 2 * t];
            const float* ax1 = &sx[(m0 + g + 8) * LDM + 2 * t];
            const float* bx  = &sc[g * LDM + 2 * t];
#pragma unroll
            for (int ks = 0; ks < 16; ++ks) {
                float2 a01 = *reinterpret_cast<const float2*>(ax0 + ks * 8);
                float2 a23 = *reinterpret_cast<const float2*>(ax1 + ks * 8);
#pragma unroll
                for (int j = 0; j < 16; ++j) {
                    float2 b = *reinterpret_cast<const float2*>(bx + j * 8 * LDM + ks * 8);
                    mma8(acc[j], a01, a23, b);
                }
            }
        }

        const int rlo = m0 + g, rhi = m0 + g + 8;
        const int lab_lo = g_cl[cs][pbase + rlo];
        const int lab_hi = g_cl[cs][pbase + rhi];

        float m_lo = -FLT_MAX, m_hi = -FLT_MAX, ll_lo = -FLT_MAX, ll_hi = -FLT_MAX;
#pragma unroll
        for (int j = 0; j < 16; ++j) {
            int c0 = j * 8 + 2 * t;
#pragma unroll
            for (int v = 0; v < 2; ++v) {
                int c = c0 + v;
                if (c < K) {
                    float l0 = acc[j][v]     * INV_T;
                    float l1 = acc[j][v + 2] * INV_T;
                    m_lo = fmaxf(m_lo, l0);
                    m_hi = fmaxf(m_hi, l1);
                    if (c == lab_lo) ll_lo = l0;
                    if (c == lab_hi) ll_hi = l1;
                }
            }
        }
#pragma unroll
        for (int off = 1; off <= 2; off <<= 1) {
            m_lo  = fmaxf(m_lo,  __shfl_xor_sync(0xffffffffu, m_lo,  off));
            m_hi  = fmaxf(m_hi,  __shfl_xor_sync(0xffffffffu, m_hi,  off));
            ll_lo = fmaxf(ll_lo, __shfl_xor_sync(0xffffffffu, ll_lo, off));
            ll_hi = fmaxf(ll_hi, __shfl_xor_sync(0xffffffffu, ll_hi, off));
        }

        float es_lo = 0.f, es_hi = 0.f;
#pragma unroll
        for (int j = 0; j < 16; ++j) {
            int c0 = j * 8 + 2 * t;
#pragma unroll
            for (int v = 0; v < 2; ++v) {
                int c = c0 + v;
                if (c < K) {
                    es_lo += expf(acc[j][v]     * INV_T - m_lo);
                    es_hi += expf(acc[j][v + 2] * INV_T - m_hi);
                }
            }
        }
#pragma unroll
        for (int off = 1; off <= 2; off <<= 1) {
            es_lo += __shfl_xor_sync(0xffffffffu, es_lo, off);
            es_hi += __shfl_xor_sync(0xffffffffu, es_hi, off);
        }

        if (t == 0) {
            float term = (m_lo + logf(es_lo)) - ll_lo
                       + (m_hi + logf(es_hi)) - ll_hi;
            atomicAdd(&s_loss, term);
        }
        __syncthreads();  // protect sx before next stage
    }

    if (tid == 0) atomicAdd(&g_loss[li], s_loss);
}

// --------------------------- launch ------------------------------------------
extern "C" void kernel_launch(void* const* d_in, const int* in_sizes, int n_in,
                              void* d_out, int out_size) {
    const float* f1 = (const float*)d_in[0];
    const float* f2 = (const float*)d_in[1];
    float* out = (float*)d_out;

    const int smem = (BP * LDM + KP * LDM) * sizeof(float);  // ~139 KB
    cudaFuncSetAttribute(assign_kernel, cudaFuncAttributeMaxDynamicSharedMemorySize, smem);
    cudaFuncSetAttribute(ce_kernel,     cudaFuncAttributeMaxDynamicSharedMemorySize, smem);

    init_centroids<<<K, DIMS>>>(f1, 0);
    init_centroids<<<K, DIMS>>>(f2, 1);

    // all iterations of set 0 first, then set 1 (L2 reuse); serpentine per iter
    for (int s = 0; s < 2; ++s) {
        const float* x = s ? f2 : f1;
        for (int it = 0; it < 5; ++it) {
            assign_kernel<<<GRID_ASSIGN, 256, smem>>>(x, s, it & 1);
            update_centroids<<<K, DIMS>>>(s);
        }
    }

    zero_loss_k<<<1, 32>>>();
    // f2 is L2-hot after set-1 iterations: run its CE first (reverse order)
    // loss2 = CE(f2 @ c1 vs cl1) -> set cs=0, li=1 ; loss1 = CE(f1 @ c2 vs cl2)
    ce_kernel<<<GRID_ASSIGN, 256, smem>>>(f2, 0, 1, 1);
    ce_kernel<<<GRID_ASSIGN, 256, smem>>>(f1, 1, 0, 0);
    write_out<<<1, 1>>>(out);
}